// round 1
// baseline (speedup 1.0000x reference)
#include <cuda_runtime.h>
#include <cuda_bf16.h>
#include <math.h>

// ---------------- problem constants ----------------
#define BB 2
#define SS 1024
#define NN (BB*SS)          // 2048 tokens
#define EE 768
#define HH 12
#define DD 64
#define II 3072
#define LL 4
#define RH 128
#define MAXD 4
#define VV 50257
#define QKVW (3*EE)         // 2304

// ---------------- scratch (device globals; no allocation allowed) ----------------
__device__ float g_h   [NN*EE];
__device__ float g_hn  [NN*EE];
__device__ float g_qkv [NN*QKVW];
__device__ float g_attn[NN*EE];
__device__ float g_ffa [NN*II];
__device__ float g_rlog[NN*MAXD];
__device__ int   g_dep [NN];
__device__ float g_loss[1];

// ---------------- embedding: h = tok_emb[ids] + pos_emb ----------------
__global__ void embed_kernel(const int* __restrict__ ids,
                             const float* __restrict__ tok,
                             const float* __restrict__ pos,
                             float* __restrict__ h) {
    int i = blockIdx.x * blockDim.x + threadIdx.x;
    if (i >= NN*EE) return;
    int n = i / EE, e = i - n*EE;
    int s = n % SS;
    h[i] = tok[(size_t)ids[n]*EE + e] + pos[(size_t)s*EE + e];
}

// ---------------- router: per token ----------------
__global__ void router_kernel(const float* __restrict__ h,
                              const float* __restrict__ w1, const float* __restrict__ b1,
                              const float* __restrict__ w2, const float* __restrict__ b2,
                              float* __restrict__ rlog, int* __restrict__ dep) {
    int n = blockIdx.x;
    int tid = threadIdx.x;   // 128 threads
    __shared__ float r1[RH];
    __shared__ float lg[MAXD];
    const float* hr = h + (size_t)n*EE;
    // r1[tid] = relu(dot(h, w1[tid]) + b1[tid])
    {
        const float4* hv = reinterpret_cast<const float4*>(hr);
        const float4* wv = reinterpret_cast<const float4*>(w1 + (size_t)tid*EE);
        float acc = b1[tid];
        #pragma unroll 4
        for (int e = 0; e < EE/4; e++) {
            float4 a = hv[e], b = wv[e];
            acc += a.x*b.x + a.y*b.y + a.z*b.z + a.w*b.w;
        }
        r1[tid] = fmaxf(acc, 0.f);
    }
    __syncthreads();
    if (tid < MAXD) {
        float acc = b2[tid];
        const float* wr = w2 + tid*RH;
        #pragma unroll 8
        for (int j = 0; j < RH; j++) acc += r1[j]*wr[j];
        lg[tid] = acc;
        rlog[n*MAXD + tid] = acc;
    }
    __syncthreads();
    if (tid == 0) {
        int best = 0; float bv = lg[0];
        #pragma unroll
        for (int m = 1; m < MAXD; m++) if (lg[m] > bv) { bv = lg[m]; best = m; }
        dep[n] = best + 1;
    }
}

// ---------------- layernorm per token ----------------
__global__ void ln_kernel(const float* __restrict__ x,
                          const float* __restrict__ g, const float* __restrict__ b,
                          float* __restrict__ y) {
    int n = blockIdx.x, tid = threadIdx.x;   // 256 threads
    __shared__ float red[256];
    __shared__ float s_mu, s_rstd;
    const float* xr = x + (size_t)n*EE;
    float s = 0.f;
    for (int e = tid; e < EE; e += 256) s += xr[e];
    red[tid] = s; __syncthreads();
    for (int o = 128; o > 0; o >>= 1) { if (tid < o) red[tid] += red[tid+o]; __syncthreads(); }
    if (tid == 0) s_mu = red[0] * (1.f/EE);
    __syncthreads();
    float mu = s_mu;
    float v = 0.f;
    for (int e = tid; e < EE; e += 256) { float d = xr[e]-mu; v += d*d; }
    red[tid] = v; __syncthreads();
    for (int o = 128; o > 0; o >>= 1) { if (tid < o) red[tid] += red[tid+o]; __syncthreads(); }
    if (tid == 0) s_rstd = rsqrtf(red[0]*(1.f/EE) + 1e-5f);
    __syncthreads();
    float rstd = s_rstd;
    float* yr = y + (size_t)n*EE;
    for (int e = tid; e < EE; e += 256) yr[e] = (xr[e]-mu)*rstd*g[e] + b[e];
}

// ---------------- SGEMM NT: C[M,Nn] (op)= act(A[M,K] * W[Nn,K]^T + bias) ----------------
// EPI: 0 = store, 1 = gelu(exact) + store, 2 = accumulate (C += v)
// BM=BN=128, BK=32, 256 threads, 8x8 register tile per thread. M multiple of 128.
template <int EPI>
__global__ __launch_bounds__(256)
void sgemm_nt(const float* __restrict__ A, const float* __restrict__ W,
              const float* __restrict__ bias, float* __restrict__ C,
              int Nn, int K) {
    __shared__ float As[128][33];
    __shared__ float Ws[128][33];
    int tid = threadIdx.x;
    int tx = tid & 15, ty = tid >> 4;
    int m0 = blockIdx.y * 128;
    int n0 = blockIdx.x * 128;
    int lk = tid & 31;        // 0..31
    int lr = tid >> 5;        // 0..7

    float acc[8][8];
    #pragma unroll
    for (int i = 0; i < 8; i++)
        #pragma unroll
        for (int j = 0; j < 8; j++) acc[i][j] = 0.f;

    for (int k0 = 0; k0 < K; k0 += 32) {
        #pragma unroll
        for (int r = 0; r < 128; r += 8) {
            As[lr + r][lk] = A[(size_t)(m0 + lr + r)*K + k0 + lk];
            int nn = n0 + lr + r;
            Ws[lr + r][lk] = (nn < Nn) ? W[(size_t)nn*K + k0 + lk] : 0.f;
        }
        __syncthreads();
        #pragma unroll
        for (int kk = 0; kk < 32; kk++) {
            float a[8], bb[8];
            #pragma unroll
            for (int i = 0; i < 8; i++) a[i] = As[ty*8 + i][kk];
            #pragma unroll
            for (int j = 0; j < 8; j++) bb[j] = Ws[tx*8 + j][kk];
            #pragma unroll
            for (int i = 0; i < 8; i++)
                #pragma unroll
                for (int j = 0; j < 8; j++) acc[i][j] += a[i]*bb[j];
        }
        __syncthreads();
    }

    #pragma unroll
    for (int i = 0; i < 8; i++) {
        int m = m0 + ty*8 + i;
        #pragma unroll
        for (int j = 0; j < 8; j++) {
            int n = n0 + tx*8 + j;
            if (n < Nn) {
                float v = acc[i][j] + (bias ? bias[n] : 0.f);
                if (EPI == 1) v = 0.5f*v*(1.0f + erff(v*0.70710678118654752f));
                size_t ci = (size_t)m*Nn + n;
                if (EPI == 2) C[ci] += v; else C[ci] = v;
            }
        }
    }
}

// ---------------- attention: one (b, h, q) per block ----------------
// scores = q.k * 0.125 + mask(0/1); softmax over ALL S keys (mask is additive, not -inf!)
__global__ void attn_kernel(const float* __restrict__ qkv, const int* __restrict__ dep,
                            int depth, float* __restrict__ out) {
    int qi = blockIdx.x, hh = blockIdx.y, b = blockIdx.z;
    int tid = threadIdx.x;   // 256
    __shared__ float q[DD];
    __shared__ float sc[SS];
    __shared__ float red[256];
    __shared__ float s_max, s_den;

    size_t rowq = ((size_t)b*SS + qi)*QKVW;
    if (tid < DD) q[tid] = qkv[rowq + hh*DD + tid];
    int dq = (dep[b*SS + qi] >= depth);
    __syncthreads();

    float lmax = -1e30f;
    for (int j = tid; j < SS; j += 256) {
        const float4* kv = reinterpret_cast<const float4*>(qkv + ((size_t)b*SS + j)*QKVW + EE + hh*DD);
        float dot = 0.f;
        #pragma unroll
        for (int d = 0; d < DD/4; d++) {
            float4 k4 = kv[d];
            dot += q[4*d]*k4.x + q[4*d+1]*k4.y + q[4*d+2]*k4.z + q[4*d+3]*k4.w;
        }
        float msk = (j <= qi && dq && dep[b*SS + j] >= depth) ? 1.f : 0.f;
        float s = dot*0.125f + msk;
        sc[j] = s;
        lmax = fmaxf(lmax, s);
    }
    red[tid] = lmax; __syncthreads();
    for (int o = 128; o > 0; o >>= 1) { if (tid < o) red[tid] = fmaxf(red[tid], red[tid+o]); __syncthreads(); }
    if (tid == 0) s_max = red[0];
    __syncthreads();
    float mx = s_max, lsum = 0.f;
    for (int j = tid; j < SS; j += 256) { float p = expf(sc[j]-mx); sc[j] = p; lsum += p; }
    red[tid] = lsum; __syncthreads();
    for (int o = 128; o > 0; o >>= 1) { if (tid < o) red[tid] += red[tid+o]; __syncthreads(); }
    if (tid == 0) s_den = red[0];
    __syncthreads();
    float inv = 1.f / s_den;

    int d = tid & (DD-1), part = tid >> 6;   // 4 partitions over j
    float acc = 0.f;
    for (int j = part; j < SS; j += 4)
        acc += sc[j] * qkv[((size_t)b*SS + j)*QKVW + 2*EE + hh*DD + d];
    red[tid] = acc; __syncthreads();
    if (tid < DD)
        out[((size_t)b*SS + qi)*EE + hh*DD + tid] =
            (red[tid] + red[tid+64] + red[tid+128] + red[tid+192]) * inv;
}

// ---------------- router aux loss ----------------
__global__ void loss_kernel(const float* __restrict__ rlog, const int* __restrict__ dep,
                            float* __restrict__ loss) {
    int tid = threadIdx.x;  // 1024
    __shared__ float red[1024];
    float p[MAXD] = {0,0,0,0};
    float ds = 0.f;
    for (int n = tid; n < NN; n += 1024) {
        float l0 = rlog[n*4+0], l1 = rlog[n*4+1], l2 = rlog[n*4+2], l3 = rlog[n*4+3];
        float m = fmaxf(fmaxf(l0,l1), fmaxf(l2,l3));
        float e0 = expf(l0-m), e1 = expf(l1-m), e2 = expf(l2-m), e3 = expf(l3-m);
        float inv = 1.f/(e0+e1+e2+e3);
        p[0] += e0*inv; p[1] += e1*inv; p[2] += e2*inv; p[3] += e3*inv;
        ds += (float)dep[n];
    }
    float sums[5];
    float vals[5] = {p[0], p[1], p[2], p[3], ds};
    for (int v = 0; v < 5; v++) {
        red[tid] = vals[v]; __syncthreads();
        for (int o = 512; o > 0; o >>= 1) { if (tid < o) red[tid] += red[tid+o]; __syncthreads(); }
        sums[v] = red[0]; __syncthreads();
    }
    if (tid == 0) {
        const float u = 1.f/MAXD;
        float lb = 0.f;
        for (int m = 0; m < MAXD; m++) {
            float mp = sums[m] / (float)NN;
            lb += u * (logf(u) - logf(mp));
        }
        lb /= MAXD;
        float sparsity = (sums[4] / (float)NN) / MAXD;
        loss[0] = 0.01f*lb + 0.001f*sparsity;
    }
}

// ---------------- tail of output: depths(float), loss, router_logits ----------------
__global__ void finalize_kernel(const int* __restrict__ dep, const float* __restrict__ rlog,
                                const float* __restrict__ loss, float* __restrict__ out) {
    int i = blockIdx.x * blockDim.x + threadIdx.x;
    size_t base = (size_t)NN * VV;
    if (i < NN) out[base + i] = (float)dep[i];
    if (i == 0) out[base + NN] = loss[0];
    if (i < NN*MAXD) out[base + NN + 1 + i] = rlog[i];
}

// ---------------- host orchestration ----------------
extern "C" void kernel_launch(void* const* d_in, const int* in_sizes, int n_in,
                              void* d_out, int out_size) {
    const int*   ids  = (const int*)  d_in[0];
    const float* tok  = (const float*)d_in[1];
    const float* pos  = (const float*)d_in[2];
    const float* rw1  = (const float*)d_in[3];
    const float* rb1  = (const float*)d_in[4];
    const float* rw2  = (const float*)d_in[5];
    const float* rb2  = (const float*)d_in[6];
    const float* wqkv = (const float*)d_in[7];
    const float* bqkv = (const float*)d_in[8];
    const float* wo   = (const float*)d_in[9];
    const float* bo   = (const float*)d_in[10];
    const float* ln1g = (const float*)d_in[11];
    const float* ln1b = (const float*)d_in[12];
    const float* ln2g = (const float*)d_in[13];
    const float* ln2b = (const float*)d_in[14];
    const float* w1   = (const float*)d_in[15];
    const float* b1   = (const float*)d_in[16];
    const float* w2   = (const float*)d_in[17];
    const float* b2   = (const float*)d_in[18];
    const float* lnfg = (const float*)d_in[19];
    const float* lnfb = (const float*)d_in[20];
    const float* lmh  = (const float*)d_in[21];
    float* out = (float*)d_out;

    float *ph, *phn, *pqkv, *pattn, *pffa, *prl, *ploss;
    int* pdep;
    cudaGetSymbolAddress((void**)&ph,    g_h);
    cudaGetSymbolAddress((void**)&phn,   g_hn);
    cudaGetSymbolAddress((void**)&pqkv,  g_qkv);
    cudaGetSymbolAddress((void**)&pattn, g_attn);
    cudaGetSymbolAddress((void**)&pffa,  g_ffa);
    cudaGetSymbolAddress((void**)&prl,   g_rlog);
    cudaGetSymbolAddress((void**)&ploss, g_loss);
    cudaGetSymbolAddress((void**)&pdep,  g_dep);

    embed_kernel<<<(NN*EE + 255)/256, 256>>>(ids, tok, pos, ph);
    router_kernel<<<NN, RH>>>(ph, rw1, rb1, rw2, rb2, prl, pdep);

    for (int depth = 1; depth <= MAXD; depth++) {
        int li = depth - 1;   // (depth-1) % L with L==MAXD==4
        // attn block
        ln_kernel<<<NN, 256>>>(ph, ln1g + li*EE, ln1b + li*EE, phn);
        {
            dim3 g(QKVW/128, NN/128);
            sgemm_nt<0><<<g, 256>>>(phn, wqkv + (size_t)li*QKVW*EE, bqkv + li*QKVW, pqkv, QKVW, EE);
        }
        attn_kernel<<<dim3(SS, HH, BB), 256>>>(pqkv, pdep, depth, pattn);
        {
            dim3 g(EE/128, NN/128);
            sgemm_nt<2><<<g, 256>>>(pattn, wo + (size_t)li*EE*EE, bo + li*EE, ph, EE, EE);
        }
        // mlp block
        ln_kernel<<<NN, 256>>>(ph, ln2g + li*EE, ln2b + li*EE, phn);
        {
            dim3 g(II/128, NN/128);
            sgemm_nt<1><<<g, 256>>>(phn, w1 + (size_t)li*II*EE, b1 + li*II, pffa, II, EE);
        }
        {
            dim3 g(EE/128, NN/128);
            sgemm_nt<2><<<g, 256>>>(pffa, w2 + (size_t)li*EE*II, b2 + li*EE, ph, EE, II);
        }
    }

    // final LN + lm_head -> logits written directly into d_out
    ln_kernel<<<NN, 256>>>(ph, lnfg, lnfb, phn);
    {
        dim3 g((VV + 127)/128, NN/128);
        sgemm_nt<0><<<g, 256>>>(phn, lmh, (const float*)nullptr, out, VV, EE);
    }

    loss_kernel<<<1, 1024>>>(prl, pdep, ploss);

    long long full = (long long)NN*VV + NN + 1 + (long long)NN*MAXD;
    if ((long long)out_size >= full)
        finalize_kernel<<<(NN*MAXD + 255)/256, 256>>>(pdep, prl, ploss, out);
}

// round 2
// speedup vs baseline: 2.5323x; 2.5323x over previous
#include <cuda_runtime.h>
#include <cuda_bf16.h>
#include <math.h>
#include <stdint.h>

// ---------------- problem constants ----------------
#define BB 2
#define SS 1024
#define NN (BB*SS)          // 2048 tokens
#define EE 768
#define HH 12
#define DD 64
#define II 3072
#define LL 4
#define RH 128
#define MAXD 4
#define VV 50257
#define QKVW (3*EE)         // 2304

// ---------------- scratch (device globals; no allocation allowed) ----------------
__device__ float g_h   [NN*EE];
__device__ float g_hn  [NN*EE];
__device__ float g_qkv [NN*QKVW];
__device__ float g_attn[NN*EE];
__device__ float g_ffa [NN*II];
__device__ float g_rlog[NN*MAXD];
__device__ int   g_dep [NN];
__device__ float g_loss[1];

// ---------------- embedding ----------------
__global__ void embed_kernel(const int* __restrict__ ids,
                             const float* __restrict__ tok,
                             const float* __restrict__ pos,
                             float* __restrict__ h) {
    int i = blockIdx.x * blockDim.x + threadIdx.x;
    if (i >= NN*EE) return;
    int n = i / EE, e = i - n*EE;
    int s = n % SS;
    h[i] = tok[(size_t)ids[n]*EE + e] + pos[(size_t)s*EE + e];
}

// ---------------- router ----------------
__global__ void router_kernel(const float* __restrict__ h,
                              const float* __restrict__ w1, const float* __restrict__ b1,
                              const float* __restrict__ w2, const float* __restrict__ b2,
                              float* __restrict__ rlog, int* __restrict__ dep) {
    int n = blockIdx.x;
    int tid = threadIdx.x;   // 128 threads
    __shared__ float r1[RH];
    __shared__ float lg[MAXD];
    const float* hr = h + (size_t)n*EE;
    {
        const float4* hv = reinterpret_cast<const float4*>(hr);
        const float4* wv = reinterpret_cast<const float4*>(w1 + (size_t)tid*EE);
        float acc = b1[tid];
        #pragma unroll 4
        for (int e = 0; e < EE/4; e++) {
            float4 a = hv[e], b = wv[e];
            acc += a.x*b.x + a.y*b.y + a.z*b.z + a.w*b.w;
        }
        r1[tid] = fmaxf(acc, 0.f);
    }
    __syncthreads();
    if (tid < MAXD) {
        float acc = b2[tid];
        const float* wr = w2 + tid*RH;
        #pragma unroll 8
        for (int j = 0; j < RH; j++) acc += r1[j]*wr[j];
        lg[tid] = acc;
        rlog[n*MAXD + tid] = acc;
    }
    __syncthreads();
    if (tid == 0) {
        int best = 0; float bv = lg[0];
        #pragma unroll
        for (int m = 1; m < MAXD; m++) if (lg[m] > bv) { bv = lg[m]; best = m; }
        dep[n] = best + 1;
    }
}

// ---------------- layernorm per token ----------------
__global__ void ln_kernel(const float* __restrict__ x,
                          const float* __restrict__ g, const float* __restrict__ b,
                          float* __restrict__ y) {
    int n = blockIdx.x, tid = threadIdx.x;   // 256 threads
    __shared__ float red[256];
    __shared__ float s_mu, s_rstd;
    const float* xr = x + (size_t)n*EE;
    float s = 0.f;
    for (int e = tid; e < EE; e += 256) s += xr[e];
    red[tid] = s; __syncthreads();
    for (int o = 128; o > 0; o >>= 1) { if (tid < o) red[tid] += red[tid+o]; __syncthreads(); }
    if (tid == 0) s_mu = red[0] * (1.f/EE);
    __syncthreads();
    float mu = s_mu;
    float v = 0.f;
    for (int e = tid; e < EE; e += 256) { float d = xr[e]-mu; v += d*d; }
    red[tid] = v; __syncthreads();
    for (int o = 128; o > 0; o >>= 1) { if (tid < o) red[tid] += red[tid+o]; __syncthreads(); }
    if (tid == 0) s_rstd = rsqrtf(red[0]*(1.f/EE) + 1e-5f);
    __syncthreads();
    float rstd = s_rstd;
    float* yr = y + (size_t)n*EE;
    for (int e = tid; e < EE; e += 256) yr[e] = (xr[e]-mu)*rstd*g[e] + b[e];
}

// ---------------- tf32 helpers ----------------
__device__ __forceinline__ void split_tf32(float x, uint32_t& hi, uint32_t& lo) {
    uint32_t h;
    asm("cvt.rna.tf32.f32 %0, %1;" : "=r"(h) : "f"(x));
    float hf = __uint_as_float(h);
    float lf = x - hf;
    uint32_t l;
    asm("cvt.rna.tf32.f32 %0, %1;" : "=r"(l) : "f"(lf));
    hi = h; lo = l;
}

__device__ __forceinline__ void mma_tf32(float* d, const uint32_t* a, const uint32_t* b) {
    asm volatile(
        "mma.sync.aligned.m16n8k8.row.col.f32.tf32.tf32.f32 "
        "{%0,%1,%2,%3}, {%4,%5,%6,%7}, {%8,%9}, {%0,%1,%2,%3};"
        : "+f"(d[0]), "+f"(d[1]), "+f"(d[2]), "+f"(d[3])
        : "r"(a[0]), "r"(a[1]), "r"(a[2]), "r"(a[3]),
          "r"(b[0]), "r"(b[1]));
}

// ---------------- GEMM NT via 3xTF32 mma: C[M,Nn] (op)= act(A[M,K] * W[Nn,K]^T + bias) ----------------
// EPI: 0 = store, 1 = gelu + store, 2 = accumulate. M multiple of 128, K multiple of 32.
template <int EPI>
__global__ __launch_bounds__(256)
void gemm_tf32(const float* __restrict__ A, const float* __restrict__ W,
               const float* __restrict__ bias, float* __restrict__ C,
               int Nn, int K) {
    __shared__ float As[128][36];
    __shared__ float Ws[128][36];
    int tid = threadIdx.x;
    int m0 = blockIdx.y * 128;
    int n0 = blockIdx.x * 128;
    int warp = tid >> 5, lane = tid & 31;
    int wm = (warp & 1) * 64;     // warp tile 64(m) x 32(n)
    int wn = (warp >> 1) * 32;
    int g = lane >> 2, t = lane & 3;

    float acc[4][4][4];
    #pragma unroll
    for (int mf = 0; mf < 4; mf++)
        #pragma unroll
        for (int nf = 0; nf < 4; nf++)
            #pragma unroll
            for (int i = 0; i < 4; i++) acc[mf][nf][i] = 0.f;

    int lrow = tid >> 3;          // 0..31
    int lk4  = (tid & 7) * 4;     // 0,4,...,28

    for (int k0 = 0; k0 < K; k0 += 32) {
        #pragma unroll
        for (int p = 0; p < 4; p++) {
            int r = lrow + p * 32;
            float4 av = *reinterpret_cast<const float4*>(&A[(size_t)(m0 + r)*K + k0 + lk4]);
            *reinterpret_cast<float4*>(&As[r][lk4]) = av;
            int nn = n0 + r;
            float4 wv = make_float4(0.f, 0.f, 0.f, 0.f);
            if (nn < Nn) wv = *reinterpret_cast<const float4*>(&W[(size_t)nn*K + k0 + lk4]);
            *reinterpret_cast<float4*>(&Ws[r][lk4]) = wv;
        }
        __syncthreads();

        #pragma unroll
        for (int ks = 0; ks < 4; ks++) {
            int kk = ks * 8;
            uint32_t ahi[4][4], alo[4][4], bhi[4][2], blo[4][2];
            #pragma unroll
            for (int mf = 0; mf < 4; mf++) {
                int mr = wm + mf*16;
                split_tf32(As[mr + g    ][kk + t    ], ahi[mf][0], alo[mf][0]);
                split_tf32(As[mr + g + 8][kk + t    ], ahi[mf][1], alo[mf][1]);
                split_tf32(As[mr + g    ][kk + t + 4], ahi[mf][2], alo[mf][2]);
                split_tf32(As[mr + g + 8][kk + t + 4], ahi[mf][3], alo[mf][3]);
            }
            #pragma unroll
            for (int nf = 0; nf < 4; nf++) {
                int nr = wn + nf*8;
                split_tf32(Ws[nr + g][kk + t    ], bhi[nf][0], blo[nf][0]);
                split_tf32(Ws[nr + g][kk + t + 4], bhi[nf][1], blo[nf][1]);
            }
            #pragma unroll
            for (int mf = 0; mf < 4; mf++)
                #pragma unroll
                for (int nf = 0; nf < 4; nf++) {
                    mma_tf32(acc[mf][nf], ahi[mf], bhi[nf]);
                    mma_tf32(acc[mf][nf], alo[mf], bhi[nf]);
                    mma_tf32(acc[mf][nf], ahi[mf], blo[nf]);
                }
        }
        __syncthreads();
    }

    // epilogue
    #pragma unroll
    for (int mf = 0; mf < 4; mf++) {
        #pragma unroll
        for (int nf = 0; nf < 4; nf++) {
            #pragma unroll
            for (int i = 0; i < 4; i++) {
                int m = m0 + wm + mf*16 + g + (i >> 1) * 8;
                int n = n0 + wn + nf*8 + t*2 + (i & 1);
                if (n < Nn) {
                    float v = acc[mf][nf][i] + (bias ? bias[n] : 0.f);
                    if (EPI == 1) v = 0.5f*v*(1.0f + erff(v*0.70710678118654752f));
                    size_t ci = (size_t)m*Nn + n;
                    if (EPI == 2) C[ci] += v; else C[ci] = v;
                }
            }
        }
    }
}

// ---------------- tiled attention: 64 q-rows per block, online softmax ----------------
// scores = q.k * 0.125 + mask(0/1 additive); softmax over ALL S keys.
__global__ __launch_bounds__(256)
void attn_tile_kernel(const float* __restrict__ qkv, const int* __restrict__ dep,
                      int depth, float* __restrict__ out) {
    extern __shared__ float sm[];
    float (*Qs)[65] = (float(*)[65])(sm);
    float (*Ks)[65] = (float(*)[65])(sm + 64*65);
    float (*Vs)[65] = (float(*)[65])(sm + 2*64*65);
    float (*Ps)[65] = (float(*)[65])(sm + 3*64*65);
    float* m_s  = sm + 4*64*65;
    float* l_s  = m_s + 64;
    float* al_s = l_s + 64;
    int*   dq_s = (int*)(al_s + 64);
    int*   dk_s = dq_s + 64;

    int qt = blockIdx.x, h = blockIdx.y, b = blockIdx.z;
    int q0 = qt * 64;
    int tid = threadIdx.x;
    int tx = tid & 15, ty = tid >> 4;

    // load Q tile + q depth flags, init stats
    {
        int d4 = (tid & 15) * 4, q = tid >> 4;
        #pragma unroll
        for (int p = 0; p < 4; p++) {
            int qq = q + p*16;
            float4 v = *reinterpret_cast<const float4*>(
                &qkv[((size_t)b*SS + q0 + qq)*QKVW + h*DD + d4]);
            Qs[qq][d4+0] = v.x; Qs[qq][d4+1] = v.y; Qs[qq][d4+2] = v.z; Qs[qq][d4+3] = v.w;
        }
    }
    if (tid < 64) {
        dq_s[tid] = (dep[b*SS + q0 + tid] >= depth) ? 1 : 0;
        m_s[tid] = -1e30f;
        l_s[tid] = 0.f;
    }

    float O[4][4];
    #pragma unroll
    for (int i = 0; i < 4; i++)
        #pragma unroll
        for (int j = 0; j < 4; j++) O[i][j] = 0.f;

    for (int k0 = 0; k0 < SS; k0 += 64) {
        __syncthreads();
        // load K,V tiles + k depth flags
        {
            int d4 = (tid & 15) * 4, j = tid >> 4;
            #pragma unroll
            for (int p = 0; p < 4; p++) {
                int jj = j + p*16;
                size_t row = ((size_t)b*SS + k0 + jj)*QKVW + h*DD;
                float4 kv = *reinterpret_cast<const float4*>(&qkv[row + EE + d4]);
                Ks[jj][d4+0] = kv.x; Ks[jj][d4+1] = kv.y; Ks[jj][d4+2] = kv.z; Ks[jj][d4+3] = kv.w;
                float4 vv = *reinterpret_cast<const float4*>(&qkv[row + 2*EE + d4]);
                Vs[jj][d4+0] = vv.x; Vs[jj][d4+1] = vv.y; Vs[jj][d4+2] = vv.z; Vs[jj][d4+3] = vv.w;
            }
        }
        if (tid < 64) dk_s[tid] = (dep[b*SS + k0 + tid] >= depth) ? 1 : 0;
        __syncthreads();

        // S = Q K^T (4x4 per thread)
        float sacc[4][4];
        #pragma unroll
        for (int i = 0; i < 4; i++)
            #pragma unroll
            for (int j = 0; j < 4; j++) sacc[i][j] = 0.f;
        #pragma unroll 8
        for (int d = 0; d < 64; d++) {
            float a[4], bb[4];
            #pragma unroll
            for (int i = 0; i < 4; i++) a[i] = Qs[ty*4+i][d];
            #pragma unroll
            for (int j = 0; j < 4; j++) bb[j] = Ks[tx*4+j][d];
            #pragma unroll
            for (int i = 0; i < 4; i++)
                #pragma unroll
                for (int j = 0; j < 4; j++) sacc[i][j] += a[i]*bb[j];
        }
        // scale + additive mask, write to Ps
        #pragma unroll
        for (int i = 0; i < 4; i++) {
            int row = ty*4 + i;
            int rowg = q0 + row;
            #pragma unroll
            for (int j = 0; j < 4; j++) {
                int col = tx*4 + j;
                int colg = k0 + col;
                float msk = (colg <= rowg && dq_s[row] && dk_s[col]) ? 1.f : 0.f;
                Ps[row][col] = sacc[i][j]*0.125f + msk;
            }
        }
        __syncthreads();

        // per-row online softmax stats (4 threads per row)
        {
            int rid = tid >> 2, sub = tid & 3;
            float mx = -1e30f;
            #pragma unroll
            for (int jj = 0; jj < 16; jj++) mx = fmaxf(mx, Ps[rid][sub*16+jj]);
            mx = fmaxf(mx, __shfl_xor_sync(0xffffffff, mx, 1));
            mx = fmaxf(mx, __shfl_xor_sync(0xffffffff, mx, 2));
            float mold = m_s[rid];
            float mnew = fmaxf(mold, mx);
            float sum = 0.f;
            #pragma unroll
            for (int jj = 0; jj < 16; jj++) {
                float p = expf(Ps[rid][sub*16+jj] - mnew);
                Ps[rid][sub*16+jj] = p;
                sum += p;
            }
            sum += __shfl_xor_sync(0xffffffff, sum, 1);
            sum += __shfl_xor_sync(0xffffffff, sum, 2);
            if (sub == 0) {
                float alpha = expf(mold - mnew);
                al_s[rid] = alpha;
                l_s[rid] = l_s[rid]*alpha + sum;
                m_s[rid] = mnew;
            }
        }
        __syncthreads();

        // O = O*alpha + P V
        float alr[4];
        #pragma unroll
        for (int i = 0; i < 4; i++) alr[i] = al_s[ty*4+i];
        #pragma unroll
        for (int i = 0; i < 4; i++)
            #pragma unroll
            for (int j = 0; j < 4; j++) O[i][j] *= alr[i];
        #pragma unroll 8
        for (int k = 0; k < 64; k++) {
            float a[4], bb[4];
            #pragma unroll
            for (int i = 0; i < 4; i++) a[i] = Ps[ty*4+i][k];
            #pragma unroll
            for (int j = 0; j < 4; j++) bb[j] = Vs[k][tx*4+j];
            #pragma unroll
            for (int i = 0; i < 4; i++)
                #pragma unroll
                for (int j = 0; j < 4; j++) O[i][j] += a[i]*bb[j];
        }
    }
    __syncthreads();

    #pragma unroll
    for (int i = 0; i < 4; i++) {
        int row = ty*4 + i;
        float inv = 1.f / l_s[row];
        #pragma unroll
        for (int j = 0; j < 4; j++) {
            out[((size_t)b*SS + q0 + row)*EE + h*DD + tx*4 + j] = O[i][j]*inv;
        }
    }
}

// ---------------- router aux loss ----------------
__global__ void loss_kernel(const float* __restrict__ rlog, const int* __restrict__ dep,
                            float* __restrict__ loss) {
    int tid = threadIdx.x;  // 1024
    __shared__ float red[1024];
    float p[MAXD] = {0,0,0,0};
    float ds = 0.f;
    for (int n = tid; n < NN; n += 1024) {
        float l0 = rlog[n*4+0], l1 = rlog[n*4+1], l2 = rlog[n*4+2], l3 = rlog[n*4+3];
        float m = fmaxf(fmaxf(l0,l1), fmaxf(l2,l3));
        float e0 = expf(l0-m), e1 = expf(l1-m), e2 = expf(l2-m), e3 = expf(l3-m);
        float inv = 1.f/(e0+e1+e2+e3);
        p[0] += e0*inv; p[1] += e1*inv; p[2] += e2*inv; p[3] += e3*inv;
        ds += (float)dep[n];
    }
    float sums[5];
    float vals[5] = {p[0], p[1], p[2], p[3], ds};
    for (int v = 0; v < 5; v++) {
        red[tid] = vals[v]; __syncthreads();
        for (int o = 512; o > 0; o >>= 1) { if (tid < o) red[tid] += red[tid+o]; __syncthreads(); }
        sums[v] = red[0]; __syncthreads();
    }
    if (tid == 0) {
        const float u = 1.f/MAXD;
        float lb = 0.f;
        for (int m = 0; m < MAXD; m++) {
            float mp = sums[m] / (float)NN;
            lb += u * (logf(u) - logf(mp));
        }
        lb /= MAXD;
        float sparsity = (sums[4] / (float)NN) / MAXD;
        loss[0] = 0.01f*lb + 0.001f*sparsity;
    }
}

// ---------------- output tail ----------------
__global__ void finalize_kernel(const int* __restrict__ dep, const float* __restrict__ rlog,
                                const float* __restrict__ loss, float* __restrict__ out) {
    int i = blockIdx.x * blockDim.x + threadIdx.x;
    size_t base = (size_t)NN * VV;
    if (i < NN) out[base + i] = (float)dep[i];
    if (i == 0) out[base + NN] = loss[0];
    if (i < NN*MAXD) out[base + NN + 1 + i] = rlog[i];
}

// ---------------- host orchestration ----------------
extern "C" void kernel_launch(void* const* d_in, const int* in_sizes, int n_in,
                              void* d_out, int out_size) {
    const int*   ids  = (const int*)  d_in[0];
    const float* tok  = (const float*)d_in[1];
    const float* pos  = (const float*)d_in[2];
    const float* rw1  = (const float*)d_in[3];
    const float* rb1  = (const float*)d_in[4];
    const float* rw2  = (const float*)d_in[5];
    const float* rb2  = (const float*)d_in[6];
    const float* wqkv = (const float*)d_in[7];
    const float* bqkv = (const float*)d_in[8];
    const float* wo   = (const float*)d_in[9];
    const float* bo   = (const float*)d_in[10];
    const float* ln1g = (const float*)d_in[11];
    const float* ln1b = (const float*)d_in[12];
    const float* ln2g = (const float*)d_in[13];
    const float* ln2b = (const float*)d_in[14];
    const float* w1   = (const float*)d_in[15];
    const float* b1   = (const float*)d_in[16];
    const float* w2   = (const float*)d_in[17];
    const float* b2   = (const float*)d_in[18];
    const float* lnfg = (const float*)d_in[19];
    const float* lnfb = (const float*)d_in[20];
    const float* lmh  = (const float*)d_in[21];
    float* out = (float*)d_out;

    float *ph, *phn, *pqkv, *pattn, *pffa, *prl, *ploss;
    int* pdep;
    cudaGetSymbolAddress((void**)&ph,    g_h);
    cudaGetSymbolAddress((void**)&phn,   g_hn);
    cudaGetSymbolAddress((void**)&pqkv,  g_qkv);
    cudaGetSymbolAddress((void**)&pattn, g_attn);
    cudaGetSymbolAddress((void**)&pffa,  g_ffa);
    cudaGetSymbolAddress((void**)&prl,   g_rlog);
    cudaGetSymbolAddress((void**)&ploss, g_loss);
    cudaGetSymbolAddress((void**)&pdep,  g_dep);

    // attention needs >48KB dynamic smem
    static const int ATTN_SMEM = (4*64*65 + 3*64) * sizeof(float) + 2*64*sizeof(int);
    cudaFuncSetAttribute(attn_tile_kernel, cudaFuncAttributeMaxDynamicSharedMemorySize, ATTN_SMEM);

    embed_kernel<<<(NN*EE + 255)/256, 256>>>(ids, tok, pos, ph);
    router_kernel<<<NN, RH>>>(ph, rw1, rb1, rw2, rb2, prl, pdep);

    for (int depth = 1; depth <= MAXD; depth++) {
        int li = depth - 1;
        ln_kernel<<<NN, 256>>>(ph, ln1g + li*EE, ln1b + li*EE, phn);
        {
            dim3 g(QKVW/128, NN/128);
            gemm_tf32<0><<<g, 256>>>(phn, wqkv + (size_t)li*QKVW*EE, bqkv + li*QKVW, pqkv, QKVW, EE);
        }
        attn_tile_kernel<<<dim3(SS/64, HH, BB), 256, ATTN_SMEM>>>(pqkv, pdep, depth, pattn);
        {
            dim3 g(EE/128, NN/128);
            gemm_tf32<2><<<g, 256>>>(pattn, wo + (size_t)li*EE*EE, bo + li*EE, ph, EE, EE);
        }
        ln_kernel<<<NN, 256>>>(ph, ln2g + li*EE, ln2b + li*EE, phn);
        {
            dim3 g(II/128, NN/128);
            gemm_tf32<1><<<g, 256>>>(phn, w1 + (size_t)li*II*EE, b1 + li*II, pffa, II, EE);
        }
        {
            dim3 g(EE/128, NN/128);
            gemm_tf32<2><<<g, 256>>>(pffa, w2 + (size_t)li*EE*II, b2 + li*EE, ph, EE, II);
        }
    }

    ln_kernel<<<NN, 256>>>(ph, lnfg, lnfb, phn);
    {
        dim3 g((VV + 127)/128, NN/128);
        gemm_tf32<0><<<g, 256>>>(phn, lmh, (const float*)nullptr, out, VV, EE);
    }

    loss_kernel<<<1, 1024>>>(prl, pdep, ploss);

    long long full = (long long)NN*VV + NN + 1 + (long long)NN*MAXD;
    if ((long long)out_size >= full)
        finalize_kernel<<<(NN*MAXD + 255)/256, 256>>>(pdep, prl, ploss, out);
}